// round 1
// baseline (speedup 1.0000x reference)
#include <cuda_runtime.h>
#include <cuda_bf16.h>

#define N_NODES 10000
#define N_EDGES 160000
#define IN_DIM  512
#define OUT_DIM 512
#define N_HOPS  3          // ORDER+1
#define LDC     (N_HOPS * OUT_DIM)   // 1536
#define VEC4    (IN_DIM / 4)         // 128 float4 per feature row

// ---------------- scratch (no allocations allowed) ----------------
__device__ float g_h1[N_NODES * IN_DIM];
__device__ float g_h2[N_NODES * IN_DIM];
__device__ int   g_counts[N_NODES];
__device__ int   g_row_ptr[N_NODES + 1];
__device__ int   g_cursor[N_NODES];
__device__ int   g_csr_src[N_EDGES];
__device__ float g_csr_w[N_EDGES];

// ---------------- CSR build (recomputed every call; deterministic) ----------------
__global__ void zero_counts_kernel() {
    int i = blockIdx.x * blockDim.x + threadIdx.x;
    if (i < N_NODES) g_counts[i] = 0;
}

__global__ void hist_kernel(const int* __restrict__ dst) {
    int e = blockIdx.x * blockDim.x + threadIdx.x;
    if (e < N_EDGES) atomicAdd(&g_counts[dst[e]], 1);
}

// single block, 1024 threads: exclusive scan of 10000 counts
__global__ void scan_kernel() {
    const int T = 1024, PER = 10;  // 1024*10 = 10240 >= 10000
    __shared__ int ssum[T];
    int t = threadIdx.x;
    int local[PER];
    int s = 0;
#pragma unroll
    for (int j = 0; j < PER; j++) {
        int idx = t * PER + j;
        int c = (idx < N_NODES) ? g_counts[idx] : 0;
        local[j] = s;
        s += c;
    }
    ssum[t] = s;
    __syncthreads();
    // Hillis-Steele inclusive scan over 1024 partials
    for (int off = 1; off < T; off <<= 1) {
        int v = (t >= off) ? ssum[t - off] : 0;
        __syncthreads();
        ssum[t] += v;
        __syncthreads();
    }
    int base = (t > 0) ? ssum[t - 1] : 0;
#pragma unroll
    for (int j = 0; j < PER; j++) {
        int idx = t * PER + j;
        if (idx < N_NODES) {
            int v = base + local[j];
            g_row_ptr[idx] = v;
            g_cursor[idx]  = v;
        }
    }
    if (t == T - 1) g_row_ptr[N_NODES] = ssum[T - 1];
}

__global__ void scatter_kernel(const int* __restrict__ src,
                               const int* __restrict__ dst,
                               const float* __restrict__ w) {
    int e = blockIdx.x * blockDim.x + threadIdx.x;
    if (e < N_EDGES) {
        int p = atomicAdd(&g_cursor[dst[e]], 1);
        g_csr_src[p] = src[e];
        g_csr_w[p]   = w[e];
    }
}

// ---------------- SpMM hop: out[n,:] = D_norm[n] * sum_{e in(n)} w_e * h_in[src_e,:] ----------------
// one block (128 threads) per node; thread t owns float4 chunk t of the 512-wide row
__global__ __launch_bounds__(128) void spmm_kernel(const float* __restrict__ h_in_ext,
                                                   const float* __restrict__ D_norm,
                                                   int hop) {
    const float* __restrict__ h_in = (hop == 1) ? h_in_ext : g_h1;
    float* __restrict__ h_out      = (hop == 1) ? g_h1 : g_h2;

    int n = blockIdx.x;
    int t = threadIdx.x;  // 0..127
    int beg = g_row_ptr[n];
    int end = g_row_ptr[n + 1];

    __shared__ int   s_src[128];
    __shared__ float s_w[128];

    float4 acc = make_float4(0.f, 0.f, 0.f, 0.f);
    for (int base = beg; base < end; base += 128) {
        int cnt = min(128, end - base);
        if (t < cnt) {
            s_src[t] = g_csr_src[base + t];
            s_w[t]   = g_csr_w[base + t];
        }
        __syncthreads();
        for (int i = 0; i < cnt; i++) {
            const float4 v = reinterpret_cast<const float4*>(h_in)[s_src[i] * VEC4 + t];
            float w = s_w[i];
            acc.x += v.x * w;
            acc.y += v.y * w;
            acc.z += v.z * w;
            acc.w += v.w * w;
        }
        __syncthreads();
    }
    float d = D_norm[n];
    float4 r = make_float4(acc.x * d, acc.y * d, acc.z * d, acc.w * d);
    reinterpret_cast<float4*>(h_out)[n * VEC4 + t] = r;
}

// ---------------- GEMM + bias + relu ----------------
// C[m, z*512 + n] = relu( A_z[m,:] @ W[z][:,n] + b[z][n] ),  A_z in {features, g_h1, g_h2}
#define BM 64
#define BN 64
#define BK 16

__global__ __launch_bounds__(256) void gemm_relu_kernel(const float* __restrict__ feat,
                                                        const float* __restrict__ W,
                                                        const float* __restrict__ bias,
                                                        float* __restrict__ out) {
    const int z = blockIdx.z;
    const float* __restrict__ A = (z == 0) ? feat : (z == 1) ? g_h1 : g_h2;
    const float* __restrict__ B = W + z * IN_DIM * OUT_DIM;   // [K=512, N=512] row-major
    const float* __restrict__ bz = bias + z * OUT_DIM;

    const int block_m = blockIdx.y * BM;
    const int block_n = blockIdx.x * BN;

    __shared__ float As[BK][BM];     // A tile transposed: As[k][m]
    __shared__ float Bs[BK][BN];

    const int tid = threadIdx.x;          // 0..255
    const int a_row = tid >> 2;           // 0..63
    const int a_col = (tid & 3) * 4;      // 0,4,8,12 (within BK)
    const int b_row = tid >> 4;           // 0..15
    const int b_col = (tid & 15) * 4;     // 0..60 (within BN)
    const int tx = tid & 15;              // 0..15 -> n
    const int ty = tid >> 4;              // 0..15 -> m

    const bool m_ok = (block_m + a_row) < N_NODES;
    const float* Aptr = A + (size_t)(block_m + a_row) * IN_DIM;

    float acc[4][4];
#pragma unroll
    for (int i = 0; i < 4; i++)
#pragma unroll
        for (int j = 0; j < 4; j++) acc[i][j] = 0.f;

    for (int k0 = 0; k0 < IN_DIM; k0 += BK) {
        float4 av = m_ok ? *reinterpret_cast<const float4*>(Aptr + k0 + a_col)
                         : make_float4(0.f, 0.f, 0.f, 0.f);
        float4 bv = *reinterpret_cast<const float4*>(B + (size_t)(k0 + b_row) * OUT_DIM + block_n + b_col);
        As[a_col + 0][a_row] = av.x;
        As[a_col + 1][a_row] = av.y;
        As[a_col + 2][a_row] = av.z;
        As[a_col + 3][a_row] = av.w;
        *reinterpret_cast<float4*>(&Bs[b_row][b_col]) = bv;
        __syncthreads();

#pragma unroll
        for (int k = 0; k < BK; k++) {
            float ar[4], br[4];
#pragma unroll
            for (int i = 0; i < 4; i++) ar[i] = As[k][ty * 4 + i];
#pragma unroll
            for (int j = 0; j < 4; j++) br[j] = Bs[k][tx * 4 + j];
#pragma unroll
            for (int i = 0; i < 4; i++)
#pragma unroll
                for (int j = 0; j < 4; j++) acc[i][j] += ar[i] * br[j];
        }
        __syncthreads();
    }

#pragma unroll
    for (int i = 0; i < 4; i++) {
        int m = block_m + ty * 4 + i;
        if (m >= N_NODES) continue;
#pragma unroll
        for (int j = 0; j < 4; j++) {
            int n = block_n + tx * 4 + j;
            float v = acc[i][j] + bz[n];
            out[(size_t)m * LDC + z * OUT_DIM + n] = fmaxf(v, 0.f);
        }
    }
}

// ---------------- launch ----------------
extern "C" void kernel_launch(void* const* d_in, const int* in_sizes, int n_in,
                              void* d_out, int out_size) {
    const float* features = (const float*)d_in[0];
    const float* D_norm   = (const float*)d_in[1];
    const float* edge_w   = (const float*)d_in[2];
    const float* W        = (const float*)d_in[3];
    const float* b        = (const float*)d_in[4];
    const int*   src      = (const int*)d_in[5];
    const int*   dst      = (const int*)d_in[6];
    float* out = (float*)d_out;

    // CSR build (by dst)
    zero_counts_kernel<<<(N_NODES + 255) / 256, 256>>>();
    hist_kernel<<<(N_EDGES + 255) / 256, 256>>>(dst);
    scan_kernel<<<1, 1024>>>();
    scatter_kernel<<<(N_EDGES + 255) / 256, 256>>>(src, dst, edge_w);

    // hop 1: features -> g_h1 ; hop 2: g_h1 -> g_h2 (D_norm fused)
    spmm_kernel<<<N_NODES, 128>>>(features, D_norm, 1);
    spmm_kernel<<<N_NODES, 128>>>(features, D_norm, 2);

    // 3 GEMMs (z dimension), bias + relu, concat into [N, 1536]
    dim3 grid(OUT_DIM / BN, (N_NODES + BM - 1) / BM, N_HOPS);
    gemm_relu_kernel<<<grid, 256>>>(features, W, b, out);
}

// round 3
// speedup vs baseline: 2.1581x; 2.1581x over previous
#include <cuda_runtime.h>
#include <cuda_bf16.h>
#include <cstdint>

#define N_NODES 10000
#define N_EDGES 160000
#define IN_DIM  512
#define OUT_DIM 512
#define N_HOPS  3
#define LDC     (N_HOPS * OUT_DIM)   // 1536
#define VEC4    (IN_DIM / 4)

// ---------------- scratch (no allocations allowed) ----------------
__device__ float g_h1[N_NODES * IN_DIM];
__device__ __nv_bfloat16 g_fhi[N_NODES * IN_DIM];
__device__ __nv_bfloat16 g_flo[N_NODES * IN_DIM];
__device__ __nv_bfloat16 g_h1hi[N_NODES * IN_DIM];
__device__ __nv_bfloat16 g_h1lo[N_NODES * IN_DIM];
__device__ __nv_bfloat16 g_h2hi[N_NODES * IN_DIM];
__device__ __nv_bfloat16 g_h2lo[N_NODES * IN_DIM];
__device__ __nv_bfloat16 g_wthi[N_HOPS * IN_DIM * OUT_DIM]; // Wt[z][n][k]
__device__ __nv_bfloat16 g_wtlo[N_HOPS * IN_DIM * OUT_DIM];
__device__ int   g_counts[N_NODES];
__device__ int   g_row_ptr[N_NODES + 1];
__device__ int   g_cursor[N_NODES];
__device__ int   g_csr_src[N_EDGES];
__device__ float g_csr_w[N_EDGES];

// ---------------- helpers ----------------
__device__ __forceinline__ uint32_t smem_u32(const void* p) {
    uint32_t a;
    asm("{ .reg .u64 t; cvta.to.shared.u64 t, %1; cvt.u32.u64 %0, t; }" : "=r"(a) : "l"(p));
    return a;
}
__device__ __forceinline__ void cp16(uint32_t saddr, const void* g) {
    asm volatile("cp.async.ca.shared.global [%0], [%1], 16;" :: "r"(saddr), "l"(g));
}
__device__ __forceinline__ void cp_commit() {
    asm volatile("cp.async.commit_group;" ::: "memory");
}
template <int N>
__device__ __forceinline__ void cp_wait() {
    asm volatile("cp.async.wait_group %0;" :: "n"(N) : "memory");
}
__device__ __forceinline__ void ldsm_x4(uint32_t* r, uint32_t addr) {
    asm volatile("ldmatrix.sync.aligned.m8n8.x4.shared.b16 {%0,%1,%2,%3}, [%4];"
                 : "=r"(r[0]), "=r"(r[1]), "=r"(r[2]), "=r"(r[3]) : "r"(addr));
}
__device__ __forceinline__ void mma16816(float* c, const uint32_t* a, const uint32_t* b) {
    asm volatile(
        "mma.sync.aligned.m16n8k16.row.col.f32.bf16.bf16.f32 "
        "{%0,%1,%2,%3}, {%4,%5,%6,%7}, {%8,%9}, {%0,%1,%2,%3};"
        : "+f"(c[0]), "+f"(c[1]), "+f"(c[2]), "+f"(c[3])
        : "r"(a[0]), "r"(a[1]), "r"(a[2]), "r"(a[3]), "r"(b[0]), "r"(b[1]));
}

// ---------------- CSR build ----------------
__global__ void zero_counts_kernel() {
    int i = blockIdx.x * blockDim.x + threadIdx.x;
    if (i < N_NODES) g_counts[i] = 0;
}
__global__ void hist_kernel(const int* __restrict__ dst) {
    int e = blockIdx.x * blockDim.x + threadIdx.x;
    if (e < N_EDGES) atomicAdd(&g_counts[dst[e]], 1);
}
__global__ void scan_kernel() {
    const int T = 1024, PER = 10;
    __shared__ int ssum[T];
    int t = threadIdx.x;
    int local[PER];
    int s = 0;
#pragma unroll
    for (int j = 0; j < PER; j++) {
        int idx = t * PER + j;
        int c = (idx < N_NODES) ? g_counts[idx] : 0;
        local[j] = s; s += c;
    }
    ssum[t] = s;
    __syncthreads();
    for (int off = 1; off < T; off <<= 1) {
        int v = (t >= off) ? ssum[t - off] : 0;
        __syncthreads();
        ssum[t] += v;
        __syncthreads();
    }
    int base = (t > 0) ? ssum[t - 1] : 0;
#pragma unroll
    for (int j = 0; j < PER; j++) {
        int idx = t * PER + j;
        if (idx < N_NODES) {
            int v = base + local[j];
            g_row_ptr[idx] = v;
            g_cursor[idx]  = v;
        }
    }
    if (t == T - 1) g_row_ptr[N_NODES] = ssum[T - 1];
}
__global__ void scatter_kernel(const int* __restrict__ src, const int* __restrict__ dst,
                               const float* __restrict__ w) {
    int e = blockIdx.x * blockDim.x + threadIdx.x;
    if (e < N_EDGES) {
        int p = atomicAdd(&g_cursor[dst[e]], 1);
        g_csr_src[p] = src[e];
        g_csr_w[p]   = w[e];
    }
}

// ---------------- bf16 split helpers ----------------
__device__ __forceinline__ void split4(float4 r, __nv_bfloat162* hi2, __nv_bfloat162* lo2) {
    __nv_bfloat162 h01 = __floats2bfloat162_rn(r.x, r.y);
    __nv_bfloat162 h23 = __floats2bfloat162_rn(r.z, r.w);
    __nv_bfloat162 l01 = __floats2bfloat162_rn(r.x - __low2float(h01), r.y - __high2float(h01));
    __nv_bfloat162 l23 = __floats2bfloat162_rn(r.z - __low2float(h23), r.w - __high2float(h23));
    hi2[0] = h01; hi2[1] = h23; lo2[0] = l01; lo2[1] = l23;
}

__global__ void convert_feat_kernel(const float* __restrict__ feat) {
    int i = blockIdx.x * blockDim.x + threadIdx.x;
    const int total = N_NODES * VEC4;
    if (i >= total) return;
    float4 r = reinterpret_cast<const float4*>(feat)[i];
    __nv_bfloat162 h[2], l[2];
    split4(r, h, l);
    reinterpret_cast<__nv_bfloat162*>(g_fhi)[i * 2 + 0] = h[0];
    reinterpret_cast<__nv_bfloat162*>(g_fhi)[i * 2 + 1] = h[1];
    reinterpret_cast<__nv_bfloat162*>(g_flo)[i * 2 + 0] = l[0];
    reinterpret_cast<__nv_bfloat162*>(g_flo)[i * 2 + 1] = l[1];
}

// transpose + split W: Wt[z][n][k] = split(W[z][k][n])
__global__ void prep_w_kernel(const float* __restrict__ W) {
    int o = blockIdx.x * blockDim.x + threadIdx.x;
    const int total = N_HOPS * IN_DIM * OUT_DIM;
    if (o >= total) return;
    int k = o & (IN_DIM - 1);
    int n = (o >> 9) & (OUT_DIM - 1);
    int z = o >> 18;
    float v = W[z * IN_DIM * OUT_DIM + k * OUT_DIM + n];
    __nv_bfloat16 h = __float2bfloat16(v);
    float lr = v - __bfloat162float(h);
    g_wthi[o] = h;
    g_wtlo[o] = __float2bfloat16(lr);
}

// ---------------- SpMM hop ----------------
__global__ __launch_bounds__(128) void spmm_kernel(const float* __restrict__ h_in_ext,
                                                   const float* __restrict__ D_norm,
                                                   int hop) {
    const float* __restrict__ h_in = (hop == 1) ? h_in_ext : g_h1;
    int n = blockIdx.x;
    int t = threadIdx.x;
    int beg = g_row_ptr[n];
    int end = g_row_ptr[n + 1];

    __shared__ int   s_src[128];
    __shared__ float s_w[128];

    float4 acc = make_float4(0.f, 0.f, 0.f, 0.f);
    for (int base = beg; base < end; base += 128) {
        int cnt = min(128, end - base);
        if (t < cnt) {
            s_src[t] = g_csr_src[base + t];
            s_w[t]   = g_csr_w[base + t];
        }
        __syncthreads();
        for (int i = 0; i < cnt; i++) {
            const float4 v = reinterpret_cast<const float4*>(h_in)[s_src[i] * VEC4 + t];
            float w = s_w[i];
            acc.x += v.x * w; acc.y += v.y * w; acc.z += v.z * w; acc.w += v.w * w;
        }
        __syncthreads();
    }
    float d = D_norm[n];
    float4 r = make_float4(acc.x * d, acc.y * d, acc.z * d, acc.w * d);

    __nv_bfloat162 h[2], l[2];
    split4(r, h, l);
    int i2 = n * (VEC4 * 2) + t * 2;
    if (hop == 1) {
        reinterpret_cast<float4*>(g_h1)[n * VEC4 + t] = r;
        reinterpret_cast<__nv_bfloat162*>(g_h1hi)[i2 + 0] = h[0];
        reinterpret_cast<__nv_bfloat162*>(g_h1hi)[i2 + 1] = h[1];
        reinterpret_cast<__nv_bfloat162*>(g_h1lo)[i2 + 0] = l[0];
        reinterpret_cast<__nv_bfloat162*>(g_h1lo)[i2 + 1] = l[1];
    } else {
        reinterpret_cast<__nv_bfloat162*>(g_h2hi)[i2 + 0] = h[0];
        reinterpret_cast<__nv_bfloat162*>(g_h2hi)[i2 + 1] = h[1];
        reinterpret_cast<__nv_bfloat162*>(g_h2lo)[i2 + 0] = l[0];
        reinterpret_cast<__nv_bfloat162*>(g_h2lo)[i2 + 1] = l[1];
    }
}

// ---------------- mma.sync GEMM + bias + relu ----------------
// CTA 128x128, 8 warps each 64(m)x32(n); BK=32 halves, cp.async double buffer.
// SMEM tile rows padded to 40 halves (80B): 16B-bank = (5*row + chunk) % 8 -> conflict-free ldmatrix.
#define TPAD_H    40
#define TROW_B    80
#define TILE_B    (128 * TROW_B)     // 10240
#define STAGE_B   (4 * TILE_B)       // 40960: Ahi, Alo, Bhi, Blo
#define KCHUNKS   16                 // 512 / 32
#define GEMM_SMEM (2 * STAGE_B)      // 81920

__global__ void __launch_bounds__(256) gemm_mma_kernel(const float* __restrict__ bias,
                                                       float* __restrict__ out) {
    extern __shared__ char sm[];

    const int tid = threadIdx.x;
    const int wid = tid >> 5, lane = tid & 31;
    const int warp_m = wid & 1, warp_n = wid >> 1;   // 2 x 4 warp grid
    const int nt = blockIdx.x, mt = blockIdx.y, z = blockIdx.z;
    const int m_base = mt * 128, n_base = nt * 128;

    const __nv_bfloat16 *Ahi, *Alo;
    if (z == 0)      { Ahi = g_fhi;  Alo = g_flo;  }
    else if (z == 1) { Ahi = g_h1hi; Alo = g_h1lo; }
    else             { Ahi = g_h2hi; Alo = g_h2lo; }
    const __nv_bfloat16* Bhi = g_wthi + (size_t)z * IN_DIM * OUT_DIM;
    const __nv_bfloat16* Blo = g_wtlo + (size_t)z * IN_DIM * OUT_DIM;

    const uint32_t s_base = smem_u32(sm);

    // per-thread load slots: 2 chunks per tile (512 chunks of 16B per tile)
    int ch0 = tid, ch1 = tid + 256;
    int r0 = ch0 >> 2, j0 = ch0 & 3;
    int r1 = ch1 >> 2, j1 = ch1 & 3;
    int am0 = min(m_base + r0, N_NODES - 1);
    int am1 = min(m_base + r1, N_NODES - 1);
    int bn0 = n_base + r0, bn1 = n_base + r1;

    auto issue_stage = [&](int s, int kc) {
        uint32_t st = s_base + s * STAGE_B;
        int kh = kc * 32;  // halves
        // A hi / lo
        cp16(st + 0 * TILE_B + r0 * TROW_B + j0 * 16, Ahi + (size_t)am0 * IN_DIM + kh + j0 * 8);
        cp16(st + 0 * TILE_B + r1 * TROW_B + j1 * 16, Ahi + (size_t)am1 * IN_DIM + kh + j1 * 8);
        cp16(st + 1 * TILE_B + r0 * TROW_B + j0 * 16, Alo + (size_t)am0 * IN_DIM + kh + j0 * 8);
        cp16(st + 1 * TILE_B + r1 * TROW_B + j1 * 16, Alo + (size_t)am1 * IN_DIM + kh + j1 * 8);
        // B hi / lo
        cp16(st + 2 * TILE_B + r0 * TROW_B + j0 * 16, Bhi + (size_t)bn0 * IN_DIM + kh + j0 * 8);
        cp16(st + 2 * TILE_B + r1 * TROW_B + j1 * 16, Bhi + (size_t)bn1 * IN_DIM + kh + j1 * 8);
        cp16(st + 3 * TILE_B + r0 * TROW_B + j0 * 16, Blo + (size_t)bn0 * IN_DIM + kh + j0 * 8);
        cp16(st + 3 * TILE_B + r1 * TROW_B + j1 * 16, Blo + (size_t)bn1 * IN_DIM + kh + j1 * 8);
        cp_commit();
    };

    float acc[4][4][4];
#pragma unroll
    for (int i = 0; i < 4; i++)
#pragma unroll
        for (int j = 0; j < 4; j++)
#pragma unroll
            for (int q = 0; q < 4; q++) acc[i][j][q] = 0.f;

    // ldmatrix lane addressing (within-tile byte offsets)
    const int a_row = warp_m * 64 + (lane & 15);
    const int a_kb  = (lane >> 4) * 16;              // k-half byte offset
    const int b_row = warp_n * 32 + (lane & 7) + ((lane >> 4) << 3);
    const int b_kb  = ((lane >> 3) & 1) * 16;

    issue_stage(0, 0);

    for (int kc = 0; kc < KCHUNKS; kc++) {
        if (kc + 1 < KCHUNKS) { issue_stage((kc + 1) & 1, kc + 1); cp_wait<1>(); }
        else                  { cp_wait<0>(); }
        __syncthreads();

        uint32_t st = s_base + (kc & 1) * STAGE_B;
#pragma unroll
        for (int kk = 0; kk < 2; kk++) {
            int kb = kk * 32;  // 16 halves = 32B
            uint32_t ahi[4][4], alo[4][4];
#pragma unroll
            for (int i = 0; i < 4; i++) {
                uint32_t aaddr = st + 0 * TILE_B + (a_row + i * 16) * TROW_B + a_kb + kb;
                ldsm_x4(ahi[i], aaddr);
                ldsm_x4(alo[i], aaddr + TILE_B);
            }
            uint32_t bhi[4][2], blo[4][2];
#pragma unroll
            for (int jp = 0; jp < 2; jp++) {   // pairs of n-frags
                uint32_t r[4];
                uint32_t baddr = st + 2 * TILE_B + (b_row + jp * 16) * TROW_B + b_kb + kb;
                ldsm_x4(r, baddr);
                bhi[jp * 2][0] = r[0]; bhi[jp * 2][1] = r[1];
                bhi[jp * 2 + 1][0] = r[2]; bhi[jp * 2 + 1][1] = r[3];
                ldsm_x4(r, baddr + TILE_B);
                blo[jp * 2][0] = r[0]; blo[jp * 2][1] = r[1];
                blo[jp * 2 + 1][0] = r[2]; blo[jp * 2 + 1][1] = r[3];
            }
#pragma unroll
            for (int i = 0; i < 4; i++)
#pragma unroll
                for (int j = 0; j < 4; j++) {
                    mma16816(acc[i][j], ahi[i], bhi[j]);
                    mma16816(acc[i][j], ahi[i], blo[j]);
                    mma16816(acc[i][j], alo[i], bhi[j]);
                }
        }
        __syncthreads();
    }

    // epilogue: bias + relu + concat
    const float* bz = bias + z * OUT_DIM;
#pragma unroll
    for (int i = 0; i < 4; i++) {
        int row0 = m_base + warp_m * 64 + i * 16 + (lane >> 2);
#pragma unroll
        for (int j = 0; j < 4; j++) {
            int col = n_base + warp_n * 32 + j * 8 + (lane & 3) * 2;
            float b0 = bz[col], b1 = bz[col + 1];
            if (row0 < N_NODES) {
                float2 v;
                v.x = fmaxf(acc[i][j][0] + b0, 0.f);
                v.y = fmaxf(acc[i][j][1] + b1, 0.f);
                *(float2*)(out + (size_t)row0 * LDC + z * OUT_DIM + col) = v;
            }
            int row1 = row0 + 8;
            if (row1 < N_NODES) {
                float2 v;
                v.x = fmaxf(acc[i][j][2] + b0, 0.f);
                v.y = fmaxf(acc[i][j][3] + b1, 0.f);
                *(float2*)(out + (size_t)row1 * LDC + z * OUT_DIM + col) = v;
            }
        }
    }
}

// ---------------- launch ----------------
extern "C" void kernel_launch(void* const* d_in, const int* in_sizes, int n_in,
                              void* d_out, int out_size) {
    const float* features = (const float*)d_in[0];
    const float* D_norm   = (const float*)d_in[1];
    const float* edge_w   = (const float*)d_in[2];
    const float* W        = (const float*)d_in[3];
    const float* b        = (const float*)d_in[4];
    const int*   src      = (const int*)d_in[5];
    const int*   dst      = (const int*)d_in[6];
    float* out = (float*)d_out;

    static_assert(GEMM_SMEM <= 227 * 1024, "smem");
    cudaFuncSetAttribute(gemm_mma_kernel, cudaFuncAttributeMaxDynamicSharedMemorySize, GEMM_SMEM);

    // CSR build
    zero_counts_kernel<<<(N_NODES + 255) / 256, 256>>>();
    hist_kernel<<<(N_EDGES + 255) / 256, 256>>>(dst);
    scan_kernel<<<1, 1024>>>();
    scatter_kernel<<<(N_EDGES + 255) / 256, 256>>>(src, dst, edge_w);

    // bf16 prep
    convert_feat_kernel<<<(N_NODES * VEC4 + 255) / 256, 256>>>(features);
    prep_w_kernel<<<(N_HOPS * IN_DIM * OUT_DIM + 255) / 256, 256>>>(W);

    // SpMM hops
    spmm_kernel<<<N_NODES, 128>>>(features, D_norm, 1);
    spmm_kernel<<<N_NODES, 128>>>(features, D_norm, 2);

    // tensor-core GEMM + bias + relu + concat
    dim3 grid(OUT_DIM / 128, (N_NODES + 127) / 128, N_HOPS);
    gemm_mma_kernel<<<grid, 256, GEMM_SMEM>>>(b, out);
}